// round 2
// baseline (speedup 1.0000x reference)
#include <cuda_runtime.h>
#include <cstdint>

#define Bn 32
#define Cn 512
#define Hn 40
#define Wn 40
#define Nn 1600
#define NCn 20
#define NOUT 25
#define STRIDEF 32.0f
#define CONF_T 0.3f
#define NMS_T 0.5f

typedef unsigned long long ull;

// ---------------- scratch (device globals; no allocations allowed) ----------
__device__ float g_boxes[Bn * Nn * 4];
__device__ float g_scores[Bn * Nn];
__device__ int   g_labels[Bn * Nn];

// ---------------- f32x2 helpers ---------------------------------------------
__device__ __forceinline__ ull pack2(float x, float y) {
    ull r; asm("mov.b64 %0, {%1, %2};" : "=l"(r) : "f"(x), "f"(y)); return r;
}
__device__ __forceinline__ void fma2(ull& d, ull a, ull b) {
    asm("fma.rn.f32x2 %0, %1, %2, %0;" : "+l"(d) : "l"(a), "l"(b));
}
__device__ __forceinline__ float2 unpack2(ull v) {
    float2 r; asm("mov.b64 {%0, %1}, %2;" : "=f"(r.x), "=f"(r.y) : "l"(v)); return r;
}
__device__ __forceinline__ float sigmoidf_(float x) {
    return 1.0f / (1.0f + expf(-x));
}

// ---------------- Kernel A: fused head, split-K across lane pairs -----------
// 800 blocks x 128 threads. Lane pair (2k, 2k+1) shares one cell; even lane
// accumulates channels [0,256), odd lane [256,512); combined via shfl_xor(1).
// Weight layout: ws[sidx(c,o)] with a 32B skew for the upper half so the two
// per-warp LDS broadcast addresses hit different banks.
extern __shared__ float smemA[];

__device__ __forceinline__ int sidx_f(int c, int o) {   // float index
    return c * 26 + o + ((c >= 256) ? 8 : 0);
}

__global__ void __launch_bounds__(128) head_kernel(
    const float* __restrict__ feat,
    const float* __restrict__ wo, const float* __restrict__ bo,
    const float* __restrict__ wc, const float* __restrict__ bc,
    const float* __restrict__ wr, const float* __restrict__ br,
    float* __restrict__ out)
{
    float* ws   = smemA;                  // 512*26 + 8 floats
    float* bias = smemA + Cn * 26 + 8;    // 25 floats
    const int tid = threadIdx.x;

    for (int i = tid; i < Cn * NOUT; i += 128) {
        int c = i / NOUT, o = i - c * NOUT;
        float w;
        if (o == 0)        w = wo[c];
        else if (o <= NCn) w = wc[(o - 1) * Cn + c];
        else               w = wr[(o - 1 - NCn) * Cn + c];
        ws[sidx_f(c, o)] = w;
    }
    if (tid < NOUT) {
        float v;
        if (tid == 0)        v = bo[0];
        else if (tid <= NCn) v = bc[tid - 1];
        else                 v = br[tid - 1 - NCn];
        bias[tid] = v;
    }
    __syncthreads();

    const int half  = tid & 1;
    const int gcell = blockIdx.x * 64 + (tid >> 1);   // 1600 % 64 == 0: no straddle
    const int b = gcell / Nn;
    const int n = gcell - b * Nn;
    const float* fp = feat + (size_t)b * Cn * Nn + (size_t)half * 256 * Nn + n;
    const ull* wp = (const ull*)ws;       // pair p of channel c at wp[c*13+p (+4 skew)]
    const int cbase  = half * 256;        // global channel base
    const int uskew  = half * 4;          // ull skew for upper half

    ull acc[12];
#pragma unroll
    for (int p = 0; p < 12; p++) acc[p] = 0ULL;
    float acc24 = 0.0f;

#pragma unroll 1
    for (int c0 = 0; c0 < 256; c0 += 8) {
        float v[8];
#pragma unroll
        for (int u = 0; u < 8; u++) v[u] = fp[(c0 + u) * Nn];
#pragma unroll
        for (int u = 0; u < 8; u++) {
            ull vv = pack2(v[u], v[u]);
            int base = (cbase + c0 + u) * 13 + uskew;
#pragma unroll
            for (int p = 0; p < 12; p++) fma2(acc[p], vv, wp[base + p]);
            acc24 = fmaf(v[u], ws[sidx_f(cbase + c0 + u, 24)], acc24);
        }
    }

    float r[25];
#pragma unroll
    for (int p = 0; p < 12; p++) {
        float2 t = unpack2(acc[p]);
        r[2 * p] = t.x; r[2 * p + 1] = t.y;
    }
    r[24] = acc24;

    // combine the two K-halves, then bias
#pragma unroll
    for (int o = 0; o < NOUT; o++) {
        r[o] += __shfl_xor_sync(0xFFFFFFFFu, r[o], 1);
        r[o] += bias[o];
    }

    if (half == 0) {
        float sig_obj = sigmoidf_(r[0]);
        float best = r[1]; int lab = 0;
#pragma unroll
        for (int k = 1; k < NCn; k++)
            if (r[1 + k] > best) { best = r[1 + k]; lab = k; }
        float score = sqrtf(sig_obj * sigmoidf_(best));

        float gx = (float)(n % Wn), gy = (float)(n / Wn);
        float cx = (sigmoidf_(r[21]) + gx) * STRIDEF;
        float cy = (sigmoidf_(r[22]) + gy) * STRIDEF;
        float bw = expf(r[23]) * STRIDEF;
        float bh = expf(r[24]) * STRIDEF;

        int idx = b * Nn + n;
        float4 bx = make_float4(cx - bw * 0.5f, cy - bh * 0.5f,
                                cx + bw * 0.5f, cy + bh * 0.5f);
        *(float4*)&g_boxes[idx * 4] = bx;
        g_scores[idx] = score;
        g_labels[idx] = lab;
        out[Bn * Nn * 5 + idx] = (float)lab;   // labels region
    }
}

// ---------------- Kernel B: warp-per-(batch,class) NMS ----------------------
// 160 blocks x 128 threads; warp w of block handles group blockIdx*4+w.
// All sync is __syncwarp — no block barriers.
#define SORT_CAP 512
#define BOX_CAP  384

__global__ void __launch_bounds__(128) nms_kernel(float* __restrict__ out)
{
    __shared__ ull           sk[4][SORT_CAP];
    __shared__ float4        sbox[4][BOX_CAP];
    __shared__ unsigned char skp[4][BOX_CAP];

    const int wid  = threadIdx.x >> 5;
    const int lane = threadIdx.x & 31;
    const int grp  = blockIdx.x * 4 + wid;       // 0..639
    const int b    = grp / NCn;
    const int cls  = grp - b * NCn;
    const int bIdx = b * Nn;

    ull*           k  = sk[wid];
    float4*        bx = sbox[wid];
    unsigned char* kp = skp[wid];

    // compact cells of this class (n ascending)
    int base = 0;
    for (int n0 = 0; n0 < Nn; n0 += 32) {
        int n = n0 + lane;
        bool m = (g_labels[bIdx + n] == cls);
        unsigned msk = __ballot_sync(0xFFFFFFFFu, m);
        if (m) {
            int pos = base + __popc(msk & ((1u << lane) - 1));
            if (pos < SORT_CAP) {
                unsigned sb = __float_as_uint(g_scores[bIdx + n]);
                k[pos] = ((ull)(~sb) << 32) | (unsigned)n;  // desc score, asc idx
            }
        }
        base += __popc(msk);
    }
    int M = base;
    if (M > BOX_CAP) M = BOX_CAP;   // statistically unreachable (M ~ 80)
    __syncwarp();

    int P = 2; while (P < M) P <<= 1;
    for (int i = M + lane; i < P; i += 32) k[i] = ~0ULL;
    __syncwarp();

    // warp bitonic sort ascending on 64-bit keys
    for (int kk = 2; kk <= P; kk <<= 1) {
        for (int j = kk >> 1; j > 0; j >>= 1) {
            for (int i = lane; i < P; i += 32) {
                int x = i ^ j;
                if (x > i) {
                    bool up = ((i & kk) == 0);
                    ull a = k[i], c = k[x];
                    if ((a > c) == up) { k[i] = c; k[x] = a; }
                }
            }
            __syncwarp();
        }
    }

    // gather boxes in sorted order; keep = conf mask
    for (int t = lane; t < M; t += 32) {
        int n = (int)(k[t] & 0xFFFFFFFFULL);
        bx[t] = *(const float4*)&g_boxes[(bIdx + n) * 4];
        float s = __uint_as_float(~(unsigned)(k[t] >> 32));
        kp[t] = (s > CONF_T) ? 1 : 0;
    }
    __syncwarp();

    // greedy suppression, warp-parallel over later boxes
    for (int i = 0; i < M; i++) {
        if (kp[i]) {
            float4 A = bx[i];
            float areaA = (A.z - A.x) * (A.w - A.y);
            for (int t = i + 1 + lane; t < M; t += 32) {
                if (kp[t]) {
                    float4 Bv = bx[t];
                    float x1 = fmaxf(A.x, Bv.x), y1 = fmaxf(A.y, Bv.y);
                    float x2 = fminf(A.z, Bv.z), y2 = fminf(A.w, Bv.w);
                    float inter = fmaxf(x2 - x1, 0.0f) * fmaxf(y2 - y1, 0.0f);
                    float areaB = (Bv.z - Bv.x) * (Bv.w - Bv.y);
                    float uni = areaA + areaB - inter;
                    if (inter / uni > NMS_T) kp[t] = 0;
                }
            }
        }
        __syncwarp();
    }

    // compose outputs for all cells of this (b,cls) group
    for (int t = lane; t < M; t += 32) {
        int n = (int)(k[t] & 0xFFFFFFFFULL);
        int idx = bIdx + n;
        bool kept = kp[t] != 0;
        float s = __uint_as_float(~(unsigned)(k[t] >> 32));
        float4 Bv = bx[t];
        out[idx * 5 + 0] = kept ? Bv.x : 0.0f;
        out[idx * 5 + 1] = kept ? Bv.y : 0.0f;
        out[idx * 5 + 2] = kept ? Bv.z : 0.0f;
        out[idx * 5 + 3] = kept ? Bv.w : 0.0f;
        out[idx * 5 + 4] = kept ? s : 0.0f;
        out[Bn * Nn * 6 + idx] = kept ? 1.0f : 0.0f;   // keep region
    }
}

// ---------------- launch -----------------------------------------------------
extern "C" void kernel_launch(void* const* d_in, const int* in_sizes, int n_in,
                              void* d_out, int out_size)
{
    const float* feat = (const float*)d_in[0];
    const float* wo   = (const float*)d_in[1];
    const float* bo   = (const float*)d_in[2];
    const float* wc   = (const float*)d_in[3];
    const float* bc   = (const float*)d_in[4];
    const float* wr   = (const float*)d_in[5];
    const float* br   = (const float*)d_in[6];
    float* out = (float*)d_out;

    size_t smem = (size_t)(Cn * 26 + 8 + 32) * sizeof(float);  // ~53.4 KB
    cudaFuncSetAttribute(head_kernel,
                         cudaFuncAttributeMaxDynamicSharedMemorySize, (int)smem);

    head_kernel<<<800, 128, smem>>>(feat, wo, bo, wc, bc, wr, br, out);
    nms_kernel<<<160, 128>>>(out);
}

// round 3
// speedup vs baseline: 1.2732x; 1.2732x over previous
#include <cuda_runtime.h>
#include <cstdint>

#define Bn 32
#define Cn 512
#define Hn 40
#define Wn 40
#define Nn 1600
#define NCn 20
#define NOUT 25
#define NGRP (Bn * NCn)     // 640
#define STRIDEF 32.0f
#define CONF_T 0.3f
#define NMS_T 0.5f

#define CAPK 256            // key slots per group
#define CAPB 192            // boxes/masks per group (M ~ Binom(1600,0.05), max ~115)

typedef unsigned long long ull;

// ---------------- scratch (device globals; no allocations allowed) ----------
__device__ float g_boxes[Bn * Nn * 4];
__device__ int   g_cnt[NGRP];
__device__ ull   g_keys[NGRP * CAPK];

// ---------------- helpers ----------------------------------------------------
__device__ __forceinline__ ull pack2(float x, float y) {
    ull r; asm("mov.b64 %0, {%1, %2};" : "=l"(r) : "f"(x), "f"(y)); return r;
}
__device__ __forceinline__ void fma2(ull& d, ull a, ull b) {
    asm("fma.rn.f32x2 %0, %1, %2, %0;" : "+l"(d) : "l"(a), "l"(b));
}
__device__ __forceinline__ float2 unpack2(ull v) {
    float2 r; asm("mov.b64 {%0, %1}, %2;" : "=f"(r.x), "=f"(r.y) : "l"(v)); return r;
}
__device__ __forceinline__ float sigmoidf_(float x) {
    return 1.0f / (1.0f + expf(-x));
}

// ---------------- init: zero the group counters ------------------------------
__global__ void init_kernel() {
    int i = blockIdx.x * blockDim.x + threadIdx.x;
    if (i < NGRP) g_cnt[i] = 0;
}

// ---------------- Kernel A: fused head, 2 cells per thread -------------------
// 400 blocks x 64 threads. Thread handles adjacent cells (2p, 2p+1): one
// float2 LDG per channel, 13 LDS.64 weight pairs shared by both cells'
// accumulators -> 0.5 LDS per FFMA2.
extern __shared__ float smemA[];

__global__ void __launch_bounds__(64) head_kernel(
    const float* __restrict__ feat,
    const float* __restrict__ wo, const float* __restrict__ bo,
    const float* __restrict__ wc, const float* __restrict__ bc,
    const float* __restrict__ wr, const float* __restrict__ br,
    float* __restrict__ out)
{
    float* ws   = smemA;               // [c*26 + o], o in [0,25)
    float* bias = smemA + Cn * 26;
    const int tid = threadIdx.x;

    // vectorized weight staging: 3200 float4 loads across the block
    for (int i = tid; i < (Cn / 4) * NOUT; i += 64) {
        int o  = i >> 7;               // 0..24
        int cq = i & 127;              // float4 index over channels
        const float* row;
        if (o == 0)       row = wo;
        else if (o <= 20) row = wc + (o - 1) * Cn;
        else              row = wr + (o - 21) * Cn;
        float4 w4 = ((const float4*)row)[cq];
        int c = cq * 4;
        ws[(c + 0) * 26 + o] = w4.x;
        ws[(c + 1) * 26 + o] = w4.y;
        ws[(c + 2) * 26 + o] = w4.z;
        ws[(c + 3) * 26 + o] = w4.w;
    }
    if (tid < NOUT) {
        float v;
        if (tid == 0)        v = bo[0];
        else if (tid <= NCn) v = bc[tid - 1];
        else                 v = br[tid - 1 - NCn];
        bias[tid] = v;
    }
    __syncthreads();

    const int pair  = blockIdx.x * 64 + tid;   // 25600 pairs
    const int cell0 = pair * 2;
    const int b  = cell0 / Nn;                 // pair never straddles batches
    const int n0 = cell0 - b * Nn;
    const float2* fp2 = (const float2*)(feat + (size_t)b * Cn * Nn + n0);
    const ull* wp = (const ull*)ws;            // pair p of channel c at wp[c*13+p]

    ull acc0[12], acc1[12];
#pragma unroll
    for (int p = 0; p < 12; p++) { acc0[p] = 0ULL; acc1[p] = 0ULL; }
    float a24x = 0.0f, a24y = 0.0f;

#pragma unroll 1
    for (int c0 = 0; c0 < Cn; c0 += 8) {
        float2 v[8];
#pragma unroll
        for (int u = 0; u < 8; u++) v[u] = fp2[(c0 + u) * (Nn / 2)];
#pragma unroll
        for (int u = 0; u < 8; u++) {
            ull va = pack2(v[u].x, v[u].x);
            ull vb = pack2(v[u].y, v[u].y);
            int base = (c0 + u) * 13;
#pragma unroll
            for (int p = 0; p < 12; p++) {
                ull w = wp[base + p];
                fma2(acc0[p], va, w);
                fma2(acc1[p], vb, w);
            }
            float w24 = ws[(c0 + u) * 26 + 24];
            a24x = fmaf(v[u].x, w24, a24x);
            a24y = fmaf(v[u].y, w24, a24y);
        }
    }

#pragma unroll
    for (int cc = 0; cc < 2; cc++) {
        float r[25];
#pragma unroll
        for (int p = 0; p < 12; p++) {
            float2 t = unpack2(cc == 0 ? acc0[p] : acc1[p]);
            r[2 * p]     = t.x + bias[2 * p];
            r[2 * p + 1] = t.y + bias[2 * p + 1];
        }
        r[24] = (cc == 0 ? a24x : a24y) + bias[24];

        // argmax over class logits == argmax over sqrt(sig*sig); first-max ties
        float sig_obj = sigmoidf_(r[0]);
        float best = r[1]; int lab = 0;
#pragma unroll
        for (int k = 1; k < NCn; k++)
            if (r[1 + k] > best) { best = r[1 + k]; lab = k; }
        float score = sqrtf(sig_obj * sigmoidf_(best));

        int n = n0 + cc;
        float gx = (float)(n % Wn), gy = (float)(n / Wn);
        float cx = (sigmoidf_(r[21]) + gx) * STRIDEF;
        float cy = (sigmoidf_(r[22]) + gy) * STRIDEF;
        float bw = expf(r[23]) * STRIDEF;
        float bh = expf(r[24]) * STRIDEF;

        int idx = b * Nn + n;
        float4 bx = make_float4(cx - bw * 0.5f, cy - bh * 0.5f,
                                cx + bw * 0.5f, cy + bh * 0.5f);
        *(float4*)&g_boxes[idx * 4] = bx;
        out[Bn * Nn * 5 + idx] = (float)lab;    // labels region

        // compact into per-(b,cls) group list (set is deterministic; NMS sorts)
        int grp = b * NCn + lab;
        int pos = atomicAdd(&g_cnt[grp], 1);
        unsigned sb = __float_as_uint(score);    // score > 0 always
        if (pos < CAPK)
            g_keys[grp * CAPK + pos] = ((ull)(~sb) << 32) | (unsigned)n;
    }
}

// ---------------- Kernel B: warp-per-group bitmask NMS ----------------------
// 160 blocks x 128 threads; warp w handles group blockIdx*4+w.
__global__ void __launch_bounds__(128) nms_kernel(float* __restrict__ out)
{
    __shared__ ull    sk[4][CAPK];
    __shared__ float4 sbox[4][CAPB];
    __shared__ ull    smask[4][CAPB * 3];

    const int wid  = threadIdx.x >> 5;
    const int lane = threadIdx.x & 31;
    const int grp  = blockIdx.x * 4 + wid;     // 0..639
    const int b    = grp / NCn;
    const int bIdx = b * Nn;

    ull*    k  = sk[wid];
    float4* bx = sbox[wid];
    ull*    mk = smask[wid];

    int M = g_cnt[grp];
    if (M > CAPB) M = CAPB;

    // load keys, pad, warp bitonic sort (key = descending score, ascending n)
    for (int t = lane; t < M; t += 32) k[t] = g_keys[grp * CAPK + t];
    int P = 1; while (P < M) P <<= 1;
    for (int i = M + lane; i < P; i += 32) k[i] = ~0ULL;
    __syncwarp();

    for (int kk = 2; kk <= P; kk <<= 1) {
        for (int j = kk >> 1; j > 0; j >>= 1) {
            for (int i = lane; i < P; i += 32) {
                int x = i ^ j;
                if (x > i) {
                    bool up = ((i & kk) == 0);
                    ull a = k[i], c = k[x];
                    if ((a > c) == up) { k[i] = c; k[x] = a; }
                }
            }
            __syncwarp();
        }
    }

    // gather boxes in rank order; count conf-passing (prefix of sorted order)
    int mc_loc = 0;
    for (int t = lane; t < M; t += 32) {
        int n = (int)(k[t] & 0xFFFFFFFFULL);
        bx[t] = *(const float4*)&g_boxes[(bIdx + n) * 4];
        float s = __uint_as_float(~(unsigned)(k[t] >> 32));
        if (s > CONF_T) mc_loc++;
    }
#pragma unroll
    for (int off = 16; off > 0; off >>= 1)
        mc_loc += __shfl_xor_sync(0xFFFFFFFFu, mc_loc, off);
    const int Mc = mc_loc;
    __syncwarp();

    // build suppression bitmasks: row i, bit j set iff j>i and IoU>thresh.
    for (int rb = 0; rb < M; rb += 32) {
        int i = rb + lane;
        ull m0 = 0, m1 = 0, m2 = 0;
        float4 A = bx[(i < M) ? i : 0];
        float areaA = (A.z - A.x) * (A.w - A.y);
        for (int j = 0; j < M; j++) {
            float4 Bv = bx[j];                       // broadcast LDS
            float x1 = fmaxf(A.x, Bv.x), y1 = fmaxf(A.y, Bv.y);
            float x2 = fminf(A.z, Bv.z), y2 = fminf(A.w, Bv.w);
            float inter = fmaxf(x2 - x1, 0.0f) * fmaxf(y2 - y1, 0.0f);
            float areaB = (Bv.z - Bv.x) * (Bv.w - Bv.y);
            float uni = areaA + areaB - inter;
            bool sup = (j > i) && (inter / uni > NMS_T);
            ull bit = sup ? (1ULL << (j & 63)) : 0ULL;
            if (j < 64)       m0 |= bit;
            else if (j < 128) m1 |= bit;
            else              m2 |= bit;
        }
        if (i < M) { mk[i * 3 + 0] = m0; mk[i * 3 + 1] = m1; mk[i * 3 + 2] = m2; }
    }
    __syncwarp();

    // serial mask reduction, replicated on all lanes (broadcast reads, no sync)
    ull kp0 = (Mc <= 0) ? 0ULL : (Mc >= 64 ? ~0ULL : ((1ULL << Mc) - 1));
    int c1 = Mc - 64;
    ull kp1 = (c1 <= 0) ? 0ULL : (c1 >= 64 ? ~0ULL : ((1ULL << c1) - 1));
    int c2 = Mc - 128;
    ull kp2 = (c2 <= 0) ? 0ULL : (c2 >= 64 ? ~0ULL : ((1ULL << c2) - 1));

#pragma unroll 4
    for (int i = 0; i < Mc; i++) {
        ull m0 = mk[i * 3 + 0], m1 = mk[i * 3 + 1], m2 = mk[i * 3 + 2];
        ull kw = (i < 64) ? kp0 : (i < 128) ? kp1 : kp2;
        if ((kw >> (i & 63)) & 1ULL) {
            kp0 &= ~m0; kp1 &= ~m1; kp2 &= ~m2;
        }
    }

    // compose outputs for all cells of this group
    for (int t = lane; t < M; t += 32) {
        int n = (int)(k[t] & 0xFFFFFFFFULL);
        int idx = bIdx + n;
        ull kw = (t < 64) ? kp0 : (t < 128) ? kp1 : kp2;
        bool kept = (kw >> (t & 63)) & 1ULL;
        float s = __uint_as_float(~(unsigned)(k[t] >> 32));
        float4 Bv = bx[t];
        out[idx * 5 + 0] = kept ? Bv.x : 0.0f;
        out[idx * 5 + 1] = kept ? Bv.y : 0.0f;
        out[idx * 5 + 2] = kept ? Bv.z : 0.0f;
        out[idx * 5 + 3] = kept ? Bv.w : 0.0f;
        out[idx * 5 + 4] = kept ? s : 0.0f;
        out[Bn * Nn * 6 + idx] = kept ? 1.0f : 0.0f;   // keep region
    }
}

// ---------------- launch -----------------------------------------------------
extern "C" void kernel_launch(void* const* d_in, const int* in_sizes, int n_in,
                              void* d_out, int out_size)
{
    const float* feat = (const float*)d_in[0];
    const float* wo   = (const float*)d_in[1];
    const float* bo   = (const float*)d_in[2];
    const float* wc   = (const float*)d_in[3];
    const float* bc   = (const float*)d_in[4];
    const float* wr   = (const float*)d_in[5];
    const float* br   = (const float*)d_in[6];
    float* out = (float*)d_out;

    size_t smem = (size_t)(Cn * 26 + 32) * sizeof(float);  // ~53.4 KB
    cudaFuncSetAttribute(head_kernel,
                         cudaFuncAttributeMaxDynamicSharedMemorySize, (int)smem);

    init_kernel<<<5, 128>>>();
    head_kernel<<<400, 64, smem>>>(feat, wo, bo, wc, bc, wr, br, out);
    nms_kernel<<<160, 128>>>(out);
}

// round 4
// speedup vs baseline: 1.4402x; 1.1311x over previous
#include <cuda_runtime.h>
#include <cstdint>

#define Bn 32
#define Cn 512
#define Hn 40
#define Wn 40
#define Nn 1600
#define NCn 20
#define NOUT 25
#define NGRP (Bn * NCn)     // 640
#define STRIDEF 32.0f
#define CONF_T 0.3f
#define NMS_T 0.5f

#define CAPK 256            // key slots per group
#define CAPB 192            // boxes/masks per group (M ~ 80 typical)

typedef unsigned long long ull;

// ---------------- scratch (device globals; zero-initialized at load) --------
__device__ float g_boxes[Bn * Nn * 4];
__device__ int   g_cnt[NGRP];           // zeroed by nms_kernel after each use
__device__ ull   g_keys[NGRP * CAPK];

// ---------------- helpers ----------------------------------------------------
__device__ __forceinline__ ull pack2(float x, float y) {
    ull r; asm("mov.b64 %0, {%1, %2};" : "=l"(r) : "f"(x), "f"(y)); return r;
}
__device__ __forceinline__ void fma2(ull& d, ull a, ull b) {
    asm("fma.rn.f32x2 %0, %1, %2, %0;" : "+l"(d) : "l"(a), "l"(b));
}
__device__ __forceinline__ float2 unpack2(ull v) {
    float2 r; asm("mov.b64 {%0, %1}, %2;" : "=f"(r.x), "=f"(r.y) : "l"(v)); return r;
}
__device__ __forceinline__ float sigmoidf_(float x) {
    return 1.0f / (1.0f + expf(-x));
}

// ---------------- Kernel A: head, 2 cells/thread x split-K(2) ---------------
// 200 blocks x 256 threads. Block covers 256 cells. Thread (half, pi):
//   half = tid>>7 selects channels [half*256, half*256+256)
//   pi   = tid&127 selects cell pair (2pi, 2pi+1) within block
// 13 LDS.64 weight pairs feed 26 FFMA2 (2 cells) -> 0.5 LDS per FFMA2.
// K-halves combined through smem (weight region reused after barrier).
extern __shared__ float smemA[];

#define TBH 256

__global__ void __launch_bounds__(TBH) head_kernel(
    const float* __restrict__ feat,
    const float* __restrict__ wo, const float* __restrict__ bo,
    const float* __restrict__ wc, const float* __restrict__ bc,
    const float* __restrict__ wr, const float* __restrict__ br,
    float* __restrict__ out)
{
    float* ws   = smemA;               // [c*26 + o], o in [0,26); slot 25 = 0
    float* bias = smemA + Cn * 26;
    const int tid = threadIdx.x;

    // stage weights (float4 over channels)
    for (int i = tid; i < (Cn / 4) * NOUT; i += TBH) {
        int o  = i >> 7;               // 0..24
        int cq = i & 127;
        const float* row;
        if (o == 0)       row = wo;
        else if (o <= 20) row = wc + (o - 1) * Cn;
        else              row = wr + (o - 21) * Cn;
        float4 w4 = ((const float4*)row)[cq];
        int c = cq * 4;
        ws[(c + 0) * 26 + o] = w4.x;
        ws[(c + 1) * 26 + o] = w4.y;
        ws[(c + 2) * 26 + o] = w4.z;
        ws[(c + 3) * 26 + o] = w4.w;
    }
    for (int c = tid; c < Cn; c += TBH) ws[c * 26 + 25] = 0.0f;  // pad slot
    if (tid < NOUT) {
        float v;
        if (tid == 0)        v = bo[0];
        else if (tid <= NCn) v = bc[tid - 1];
        else                 v = br[tid - 1 - NCn];
        bias[tid] = v;
    }
    __syncthreads();

    const int half = tid >> 7;                      // K-half
    const int pi   = tid & 127;                     // cell pair in block
    const int cell0 = blockIdx.x * 256 + pi * 2;    // even; never straddles batch
    const int b  = cell0 / Nn;
    const int n0 = cell0 - b * Nn;
    const float2* fp2 = (const float2*)(feat + (size_t)b * Cn * Nn
                                             + (size_t)half * 256 * Nn + n0);
    const ull* wp = (const ull*)ws;                 // pair p of channel c: wp[c*13+p]
    const int cb = half * 256;

    ull acc0[13], acc1[13];
#pragma unroll
    for (int p = 0; p < 13; p++) { acc0[p] = 0ULL; acc1[p] = 0ULL; }

    float2 va[8], vb[8];
#pragma unroll
    for (int u = 0; u < 8; u++) va[u] = fp2[u * (Nn / 2)];

#pragma unroll 1
    for (int c0 = 0; c0 < 256; c0 += 16) {
        // prefetch second sub-chunk
#pragma unroll
        for (int u = 0; u < 8; u++) vb[u] = fp2[(c0 + 8 + u) * (Nn / 2)];
        // compute with va (channels c0..c0+7)
#pragma unroll
        for (int u = 0; u < 8; u++) {
            ull x = pack2(va[u].x, va[u].x);
            ull y = pack2(va[u].y, va[u].y);
            int base = (cb + c0 + u) * 13;
#pragma unroll
            for (int p = 0; p < 13; p++) {
                ull w = wp[base + p];
                fma2(acc0[p], x, w);
                fma2(acc1[p], y, w);
            }
        }
        // prefetch next chunk's first sub-chunk (predicated off on last iter)
        bool more = (c0 + 16) < 256;
#pragma unroll
        for (int u = 0; u < 8; u++)
            va[u] = more ? fp2[(c0 + 16 + u) * (Nn / 2)] : make_float2(0.f, 0.f);
        // compute with vb (channels c0+8..c0+15)
#pragma unroll
        for (int u = 0; u < 8; u++) {
            ull x = pack2(vb[u].x, vb[u].x);
            ull y = pack2(vb[u].y, vb[u].y);
            int base = (cb + c0 + 8 + u) * 13;
#pragma unroll
            for (int p = 0; p < 13; p++) {
                ull w = wp[base + p];
                fma2(acc0[p], x, w);
                fma2(acc1[p], y, w);
            }
        }
    }

    float r[2][26];
#pragma unroll
    for (int p = 0; p < 13; p++) {
        float2 t0 = unpack2(acc0[p]);
        float2 t1 = unpack2(acc1[p]);
        r[0][2 * p] = t0.x; r[0][2 * p + 1] = t0.y;
        r[1][2 * p] = t1.x; r[1][2 * p + 1] = t1.y;
    }

    // exchange: half-1 partials through smem (weight region reused)
    __syncthreads();
    if (half == 1) {
#pragma unroll
        for (int cc = 0; cc < 2; cc++)
#pragma unroll
            for (int o = 0; o < NOUT; o++)
                ws[(pi * 2 + cc) * 26 + o] = r[cc][o];
    }
    __syncthreads();

    if (half == 0) {
#pragma unroll
        for (int cc = 0; cc < 2; cc++) {
            float rr[25];
#pragma unroll
            for (int o = 0; o < NOUT; o++)
                rr[o] = r[cc][o] + ws[(pi * 2 + cc) * 26 + o] + bias[o];

            float sig_obj = sigmoidf_(rr[0]);
            float best = rr[1]; int lab = 0;
#pragma unroll
            for (int k = 1; k < NCn; k++)
                if (rr[1 + k] > best) { best = rr[1 + k]; lab = k; }
            float score = sqrtf(sig_obj * sigmoidf_(best));

            int n = n0 + cc;
            float gx = (float)(n % Wn), gy = (float)(n / Wn);
            float cx = (sigmoidf_(rr[21]) + gx) * STRIDEF;
            float cy = (sigmoidf_(rr[22]) + gy) * STRIDEF;
            float bw = expf(rr[23]) * STRIDEF;
            float bh = expf(rr[24]) * STRIDEF;

            int idx = b * Nn + n;
            float4 bx = make_float4(cx - bw * 0.5f, cy - bh * 0.5f,
                                    cx + bw * 0.5f, cy + bh * 0.5f);
            *(float4*)&g_boxes[idx * 4] = bx;
            out[Bn * Nn * 5 + idx] = (float)lab;    // labels region

            int grp = b * NCn + lab;
            int pos = atomicAdd(&g_cnt[grp], 1);
            unsigned sb = __float_as_uint(score);    // score > 0 always
            if (pos < CAPK)
                g_keys[grp * CAPK + pos] = ((ull)(~sb) << 32) | (unsigned)n;
        }
    }
}

// ---------------- Kernel B: warp-per-group bitmask NMS ----------------------
__global__ void __launch_bounds__(128) nms_kernel(float* __restrict__ out)
{
    __shared__ ull    sk[4][CAPK];
    __shared__ float4 sbox[4][CAPB];
    __shared__ ull    smask[4][CAPB * 3];

    const int wid  = threadIdx.x >> 5;
    const int lane = threadIdx.x & 31;
    const int grp  = blockIdx.x * 4 + wid;     // 0..639
    const int b    = grp / NCn;
    const int bIdx = b * Nn;

    ull*    k  = sk[wid];
    float4* bx = sbox[wid];
    ull*    mk = smask[wid];

    int M = g_cnt[grp];
    if (M > CAPB) M = CAPB;
    if (lane == 0) g_cnt[grp] = 0;             // re-arm for next graph replay

    for (int t = lane; t < M; t += 32) k[t] = g_keys[grp * CAPK + t];
    int P = 1; while (P < M) P <<= 1;
    for (int i = M + lane; i < P; i += 32) k[i] = ~0ULL;
    __syncwarp();

    // warp bitonic sort ascending (key = descending score, ascending n)
    for (int kk = 2; kk <= P; kk <<= 1) {
        for (int j = kk >> 1; j > 0; j >>= 1) {
            for (int i = lane; i < P; i += 32) {
                int x = i ^ j;
                if (x > i) {
                    bool up = ((i & kk) == 0);
                    ull a = k[i], c = k[x];
                    if ((a > c) == up) { k[i] = c; k[x] = a; }
                }
            }
            __syncwarp();
        }
    }

    // gather boxes in rank order; count conf-passing (a prefix of sorted order)
    int mc_loc = 0;
    for (int t = lane; t < M; t += 32) {
        int n = (int)(k[t] & 0xFFFFFFFFULL);
        bx[t] = *(const float4*)&g_boxes[(bIdx + n) * 4];
        float s = __uint_as_float(~(unsigned)(k[t] >> 32));
        if (s > CONF_T) mc_loc++;
    }
#pragma unroll
    for (int off = 16; off > 0; off >>= 1)
        mc_loc += __shfl_xor_sync(0xFFFFFFFFu, mc_loc, off);
    const int Mc = mc_loc;
    __syncwarp();

    // suppression bitmasks: row i, bit j set iff j>i and IoU>thresh
    for (int rb = 0; rb < M; rb += 32) {
        int i = rb + lane;
        ull m0 = 0, m1 = 0, m2 = 0;
        float4 A = bx[(i < M) ? i : 0];
        float areaA = (A.z - A.x) * (A.w - A.y);
        for (int j = 0; j < M; j++) {
            float4 Bv = bx[j];                       // broadcast LDS
            float x1 = fmaxf(A.x, Bv.x), y1 = fmaxf(A.y, Bv.y);
            float x2 = fminf(A.z, Bv.z), y2 = fminf(A.w, Bv.w);
            float inter = fmaxf(x2 - x1, 0.0f) * fmaxf(y2 - y1, 0.0f);
            float areaB = (Bv.z - Bv.x) * (Bv.w - Bv.y);
            float uni = areaA + areaB - inter;
            bool sup = (j > i) && (inter / uni > NMS_T);
            ull bit = sup ? (1ULL << (j & 63)) : 0ULL;
            if (j < 64)       m0 |= bit;
            else if (j < 128) m1 |= bit;
            else              m2 |= bit;
        }
        if (i < M) { mk[i * 3 + 0] = m0; mk[i * 3 + 1] = m1; mk[i * 3 + 2] = m2; }
    }
    __syncwarp();

    // serial mask reduction, replicated on all lanes (no syncs)
    ull kp0 = (Mc <= 0) ? 0ULL : (Mc >= 64 ? ~0ULL : ((1ULL << Mc) - 1));
    int c1 = Mc - 64;
    ull kp1 = (c1 <= 0) ? 0ULL : (c1 >= 64 ? ~0ULL : ((1ULL << c1) - 1));
    int c2 = Mc - 128;
    ull kp2 = (c2 <= 0) ? 0ULL : (c2 >= 64 ? ~0ULL : ((1ULL << c2) - 1));

#pragma unroll 4
    for (int i = 0; i < Mc; i++) {
        ull m0 = mk[i * 3 + 0], m1 = mk[i * 3 + 1], m2 = mk[i * 3 + 2];
        ull kw = (i < 64) ? kp0 : (i < 128) ? kp1 : kp2;
        if ((kw >> (i & 63)) & 1ULL) {
            kp0 &= ~m0; kp1 &= ~m1; kp2 &= ~m2;
        }
    }

    // compose outputs
    for (int t = lane; t < M; t += 32) {
        int n = (int)(k[t] & 0xFFFFFFFFULL);
        int idx = bIdx + n;
        ull kw = (t < 64) ? kp0 : (t < 128) ? kp1 : kp2;
        bool kept = (kw >> (t & 63)) & 1ULL;
        float s = __uint_as_float(~(unsigned)(k[t] >> 32));
        float4 Bv = bx[t];
        out[idx * 5 + 0] = kept ? Bv.x : 0.0f;
        out[idx * 5 + 1] = kept ? Bv.y : 0.0f;
        out[idx * 5 + 2] = kept ? Bv.z : 0.0f;
        out[idx * 5 + 3] = kept ? Bv.w : 0.0f;
        out[idx * 5 + 4] = kept ? s : 0.0f;
        out[Bn * Nn * 6 + idx] = kept ? 1.0f : 0.0f;   // keep region
    }
}

// ---------------- launch -----------------------------------------------------
extern "C" void kernel_launch(void* const* d_in, const int* in_sizes, int n_in,
                              void* d_out, int out_size)
{
    const float* feat = (const float*)d_in[0];
    const float* wo   = (const float*)d_in[1];
    const float* bo   = (const float*)d_in[2];
    const float* wc   = (const float*)d_in[3];
    const float* bc   = (const float*)d_in[4];
    const float* wr   = (const float*)d_in[5];
    const float* br   = (const float*)d_in[6];
    float* out = (float*)d_out;

    size_t smem = (size_t)(Cn * 26 + 32) * sizeof(float);  // ~53.4 KB
    cudaFuncSetAttribute(head_kernel,
                         cudaFuncAttributeMaxDynamicSharedMemorySize, (int)smem);

    head_kernel<<<200, TBH, smem>>>(feat, wo, bo, wc, bc, wr, br, out);
    nms_kernel<<<160, 128>>>(out);
}

// round 8
// speedup vs baseline: 2.2241x; 1.5443x over previous
#include <cuda_runtime.h>
#include <cstdint>

#define Bn 32
#define Cn 512
#define Hn 40
#define Wn 40
#define Nn 1600
#define NCn 20
#define NOUT 25
#define NGRP (Bn * NCn)     // 640
#define STRIDEF 32.0f
#define CONF_T 0.3f
#define NMS_T 0.5f

#define CAPK 256
#define CAPB 192

typedef unsigned long long ull;

// ---------------- scratch (device globals; zero-initialized at load) --------
__device__ float g_boxes[Bn * Nn * 4];
__device__ int   g_cnt[NGRP];           // re-zeroed by nms_kernel each replay
__device__ ull   g_keys[NGRP * CAPK];

// ---------------- helpers ----------------------------------------------------
__device__ __forceinline__ ull pack2(float x, float y) {
    ull r; asm("mov.b64 %0, {%1, %2};" : "=l"(r) : "f"(x), "f"(y)); return r;
}
__device__ __forceinline__ void fma2(ull& d, ull a, ull b) {
    asm("fma.rn.f32x2 %0, %1, %2, %0;" : "+l"(d) : "l"(a), "l"(b));
}
__device__ __forceinline__ float2 unpack2(ull v) {
    float2 r; asm("mov.b64 {%0, %1}, %2;" : "=f"(r.x), "=f"(r.y) : "l"(v)); return r;
}
__device__ __forceinline__ float sigmoidf_(float x) {
    return 1.0f / (1.0f + expf(-x));
}

// ---------------- Kernel A: head, 4 cells/thread x split-K(4) ---------------
// 400 blocks x 128 threads. Warp q (=tid>>5) owns channel quarter q; lane l
// owns cells blockIdx*128 + l*4 .. +3 (float4 feat loads; warp covers 128
// contiguous cells -> coalesced). 13 LDS.64 weight pairs feed 52 FFMA2.
// Quarters combined through recycled weight smem region.
extern __shared__ float smemA[];
#define WS_FLOATS (Cn * 26)           // 13312; also = 4 * 128 * 26 partials

__global__ void __launch_bounds__(128) head_kernel(
    const float* __restrict__ feat,
    const float* __restrict__ wo, const float* __restrict__ bo,
    const float* __restrict__ wc, const float* __restrict__ bc,
    const float* __restrict__ wr, const float* __restrict__ br,
    float* __restrict__ out)
{
    float* ws   = smemA;               // [c*26 + o]; slot 25 zero pad
    float* bias = smemA + WS_FLOATS;
    const int tid = threadIdx.x;

    for (int i = tid; i < (Cn / 4) * NOUT; i += 128) {
        int o  = i >> 7;               // 0..24
        int cq = i & 127;
        const float* row;
        if (o == 0)       row = wo;
        else if (o <= 20) row = wc + (o - 1) * Cn;
        else              row = wr + (o - 21) * Cn;
        float4 w4 = ((const float4*)row)[cq];
        int c = cq * 4;
        ws[(c + 0) * 26 + o] = w4.x;
        ws[(c + 1) * 26 + o] = w4.y;
        ws[(c + 2) * 26 + o] = w4.z;
        ws[(c + 3) * 26 + o] = w4.w;
    }
    for (int c = tid; c < Cn; c += 128) ws[c * 26 + 25] = 0.0f;
    if (tid < NOUT) {
        float v;
        if (tid == 0)        v = bo[0];
        else if (tid <= NCn) v = bc[tid - 1];
        else                 v = br[tid - 1 - NCn];
        bias[tid] = v;
    }
    __syncthreads();

    const int q    = tid >> 5;                      // K-quarter (= warp)
    const int lane = tid & 31;                      // cell slot
    const int cell0 = blockIdx.x * 128 + lane * 4;  // mult of 4; no batch straddle
    const int b  = cell0 / Nn;
    const int n0 = cell0 - b * Nn;
    const float* fp = feat + (size_t)b * Cn * Nn + (size_t)q * 128 * Nn + n0;
    const ull* wp = (const ull*)ws;
    const int cb = q * 128;

    ull acc[4][13];
#pragma unroll
    for (int cc = 0; cc < 4; cc++)
#pragma unroll
        for (int p = 0; p < 13; p++) acc[cc][p] = 0ULL;

#pragma unroll 1
    for (int c0 = 0; c0 < 128; c0 += 8) {
        float4 v[8];
#pragma unroll
        for (int u = 0; u < 8; u++) v[u] = *(const float4*)(fp + (c0 + u) * Nn);
#pragma unroll
        for (int u = 0; u < 8; u++) {
            ull xx = pack2(v[u].x, v[u].x);
            ull yy = pack2(v[u].y, v[u].y);
            ull zz = pack2(v[u].z, v[u].z);
            ull qq = pack2(v[u].w, v[u].w);
            int base = (cb + c0 + u) * 13;
#pragma unroll
            for (int p = 0; p < 13; p++) {
                ull w = wp[base + p];
                fma2(acc[0][p], xx, w);
                fma2(acc[1][p], yy, w);
                fma2(acc[2][p], zz, w);
                fma2(acc[3][p], qq, w);
            }
        }
    }

    // dump partials into recycled weight region: part[q*3328 + cell_local*26 + o]
    __syncthreads();
#pragma unroll
    for (int cc = 0; cc < 4; cc++) {
        int cl = lane * 4 + cc;                 // cell_local 0..127
        float* dst = ws + q * 3328 + cl * 26;
#pragma unroll
        for (int p = 0; p < 13; p++) {
            float2 t = unpack2(acc[cc][p]);
            dst[2 * p] = t.x;
            if (2 * p + 1 < NOUT) dst[2 * p + 1] = t.y;
        }
    }
    __syncthreads();

    // epilogue: one cell per thread
    {
        int cl = tid;
        int cell = blockIdx.x * 128 + cl;
        int eb = cell / Nn;
        int n  = cell - eb * Nn;
        float rr[25];
#pragma unroll
        for (int o = 0; o < NOUT; o++)
            rr[o] = ws[0 * 3328 + cl * 26 + o] + ws[1 * 3328 + cl * 26 + o]
                  + ws[2 * 3328 + cl * 26 + o] + ws[3 * 3328 + cl * 26 + o]
                  + bias[o];

        float sig_obj = sigmoidf_(rr[0]);
        float best = rr[1]; int lab = 0;
#pragma unroll
        for (int k = 1; k < NCn; k++)
            if (rr[1 + k] > best) { best = rr[1 + k]; lab = k; }
        float score = sqrtf(sig_obj * sigmoidf_(best));

        float gx = (float)(n % Wn), gy = (float)(n / Wn);
        float cx = (sigmoidf_(rr[21]) + gx) * STRIDEF;
        float cy = (sigmoidf_(rr[22]) + gy) * STRIDEF;
        float bw = expf(rr[23]) * STRIDEF;
        float bh = expf(rr[24]) * STRIDEF;

        int idx = eb * Nn + n;
        float4 bx = make_float4(cx - bw * 0.5f, cy - bh * 0.5f,
                                cx + bw * 0.5f, cy + bh * 0.5f);
        *(float4*)&g_boxes[idx * 4] = bx;
        out[Bn * Nn * 5 + idx] = (float)lab;    // labels region

        int grp = eb * NCn + lab;
        int pos = atomicAdd(&g_cnt[grp], 1);
        unsigned sb = __float_as_uint(score);   // score > 0 always
        if (pos < CAPK)
            g_keys[grp * CAPK + pos] = ((ull)(~sb) << 32) | (unsigned)n;
    }
}

// ---------------- Kernel B: block-per-group bitmask NMS (no division) -------
__global__ void __launch_bounds__(128) nms_kernel(float* __restrict__ out)
{
    __shared__ ull    k[CAPK];
    __shared__ float4 bx[CAPB];
    __shared__ ull    mk[CAPB * 3];
    __shared__ int    scnt;

    const int tid = threadIdx.x;
    const int grp = blockIdx.x;                // 0..639
    const int b   = grp / NCn;
    const int bIdx = b * Nn;

    int M = g_cnt[grp];                        // ALL threads read M first
    if (M > CAPB) M = CAPB;
    if (tid == 0) scnt = 0;

    for (int t = tid; t < M; t += 128) k[t] = g_keys[grp * CAPK + t];
    int P = 1; while (P < M) P <<= 1;
    for (int i = M + tid; i < P; i += 128) k[i] = ~0ULL;
    __syncthreads();                           // everyone has read g_cnt by now
    if (tid == 0) g_cnt[grp] = 0;              // re-arm AFTER the barrier

    // block bitonic sort ascending (key = desc score, asc n)
    for (int kk = 2; kk <= P; kk <<= 1) {
        for (int j = kk >> 1; j > 0; j >>= 1) {
            for (int i = tid; i < P; i += 128) {
                int x = i ^ j;
                if (x > i) {
                    bool up = ((i & kk) == 0);
                    ull a = k[i], c = k[x];
                    if ((a > c) == up) { k[i] = c; k[x] = a; }
                }
            }
            __syncthreads();
        }
    }

    // gather boxes in rank order; count conf-passing (prefix of sorted order)
    int mc_loc = 0;
    for (int t = tid; t < M; t += 128) {
        int n = (int)(k[t] & 0xFFFFFFFFULL);
        bx[t] = *(const float4*)&g_boxes[(bIdx + n) * 4];
        float s = __uint_as_float(~(unsigned)(k[t] >> 32));
        if (s > CONF_T) mc_loc++;
    }
    if (mc_loc) atomicAdd(&scnt, mc_loc);
    __syncthreads();
    const int Mc = scnt;

    // suppression bitmasks: row t, bit j set iff j>t and IoU>thresh (div-free)
    for (int t = tid; t < M; t += 128) {
        ull m0 = 0, m1 = 0, m2 = 0;
        float4 A = bx[t];
        float areaA = (A.z - A.x) * (A.w - A.y);
        for (int j = t + 1; j < M; j++) {
            float4 Bv = bx[j];
            float x1 = fmaxf(A.x, Bv.x), y1 = fmaxf(A.y, Bv.y);
            float x2 = fminf(A.z, Bv.z), y2 = fminf(A.w, Bv.w);
            float inter = fmaxf(x2 - x1, 0.0f) * fmaxf(y2 - y1, 0.0f);
            float areaB = (Bv.z - Bv.x) * (Bv.w - Bv.y);
            float uni = areaA + areaB - inter;
            bool sup = inter > NMS_T * uni;
            ull bit = sup ? (1ULL << (j & 63)) : 0ULL;
            if (j < 64)       m0 |= bit;
            else if (j < 128) m1 |= bit;
            else              m2 |= bit;
        }
        mk[t * 3 + 0] = m0; mk[t * 3 + 1] = m1; mk[t * 3 + 2] = m2;
    }
    __syncthreads();

    // serial mask reduction, replicated on all threads (broadcast LDS, no sync)
    ull kp0 = (Mc <= 0) ? 0ULL : (Mc >= 64 ? ~0ULL : ((1ULL << Mc) - 1));
    int c1 = Mc - 64;
    ull kp1 = (c1 <= 0) ? 0ULL : (c1 >= 64 ? ~0ULL : ((1ULL << c1) - 1));
    int c2 = Mc - 128;
    ull kp2 = (c2 <= 0) ? 0ULL : (c2 >= 64 ? ~0ULL : ((1ULL << c2) - 1));

#pragma unroll 4
    for (int i = 0; i < Mc; i++) {
        ull m0 = mk[i * 3 + 0], m1 = mk[i * 3 + 1], m2 = mk[i * 3 + 2];
        ull kw = (i < 64) ? kp0 : (i < 128) ? kp1 : kp2;
        if ((kw >> (i & 63)) & 1ULL) {
            kp0 &= ~m0; kp1 &= ~m1; kp2 &= ~m2;
        }
    }

    // compose outputs
    for (int t = tid; t < M; t += 128) {
        int n = (int)(k[t] & 0xFFFFFFFFULL);
        int idx = bIdx + n;
        ull kw = (t < 64) ? kp0 : (t < 128) ? kp1 : kp2;
        bool kept = (kw >> (t & 63)) & 1ULL;
        float s = __uint_as_float(~(unsigned)(k[t] >> 32));
        float4 Bv = bx[t];
        out[idx * 5 + 0] = kept ? Bv.x : 0.0f;
        out[idx * 5 + 1] = kept ? Bv.y : 0.0f;
        out[idx * 5 + 2] = kept ? Bv.z : 0.0f;
        out[idx * 5 + 3] = kept ? Bv.w : 0.0f;
        out[idx * 5 + 4] = kept ? s : 0.0f;
        out[Bn * Nn * 6 + idx] = kept ? 1.0f : 0.0f;   // keep region
    }
}

// ---------------- launch -----------------------------------------------------
extern "C" void kernel_launch(void* const* d_in, const int* in_sizes, int n_in,
                              void* d_out, int out_size)
{
    const float* feat = (const float*)d_in[0];
    const float* wo   = (const float*)d_in[1];
    const float* bo   = (const float*)d_in[2];
    const float* wc   = (const float*)d_in[3];
    const float* bc   = (const float*)d_in[4];
    const float* wr   = (const float*)d_in[5];
    const float* br   = (const float*)d_in[6];
    float* out = (float*)d_out;

    size_t smem = (size_t)(WS_FLOATS + 32) * sizeof(float);  // ~53.4 KB
    cudaFuncSetAttribute(head_kernel,
                         cudaFuncAttributeMaxDynamicSharedMemorySize, (int)smem);

    head_kernel<<<400, 128, smem>>>(feat, wo, bo, wc, bc, wr, br, out);
    nms_kernel<<<NGRP, 128>>>(out);
}